// round 2
// baseline (speedup 1.0000x reference)
#include <cuda_runtime.h>
#include <math.h>
#include <stdint.h>

#define TT 700
#define BB 32
#define HH 800
#define K1 1600
#define DINX 53
#define GRID 148
#define NW 11
#define NTHR (NW * 32)

// ---------------- scratch (static device globals; no allocation) ----------------
__device__ float d_xT [TT * 64 * BB];         // [t][k(64 padded)][b]
__device__ float d_h0T[TT * K1 * BB];         // [t][row 0..1599][b]  f=[0,800) b=[800,1600)
__device__ float d_h1T[TT * K1 * BB];
__device__ float d_xg [2 * TT * 3200 * BB];   // [dir][t][gate-row 0..3199][b]  (bias folded in)
__device__ float d_Wt0f[DINX * 3200];         // transposed Wih0: [k][row]
__device__ float d_Wt0b[DINX * 3200];
__device__ float d_Wt1f[K1 * 3200];
__device__ float d_Wt1b[K1 * 3200];
__device__ float d_dih[TT * BB * 3];

// global barrier state (zero-initialized)
__device__ unsigned g_cnt[8];
__device__ unsigned g_master;
__device__ volatile unsigned g_gen;

// ---------------- prep: x = concat(emb[primary], evolutionary), transposed ----------------
__global__ void k_prep(const int* __restrict__ primary,
                       const float* __restrict__ evo,
                       const float* __restrict__ emb)
{
    int idx = blockIdx.x * blockDim.x + threadIdx.x;
    if (idx >= TT * 64 * BB) return;
    int b = idx & 31;
    int k = (idx >> 5) & 63;
    int t = idx >> 11;
    float v = 0.f;
    if (k < 32) {
        int aa = primary[t * BB + b];
        v = emb[aa * 32 + k];
    } else if (k < DINX) {
        v = evo[(t * BB + b) * 21 + (k - 32)];
    }
    d_xT[idx] = v;
}

// ---------------- transpose input weights into [k][row] ----------------
__global__ void k_trans(const float* __restrict__ W0f, const float* __restrict__ W0b,
                        const float* __restrict__ W1f, const float* __restrict__ W1b)
{
    const int N0 = 3200 * DINX;
    const int N1 = 3200 * K1;
    const int NT = 2 * N0 + 2 * N1;
    for (int i = blockIdx.x * blockDim.x + threadIdx.x; i < NT; i += gridDim.x * blockDim.x) {
        if (i < N0) {
            int r = i / DINX, k = i % DINX;
            d_Wt0f[k * 3200 + r] = W0f[i];
        } else if (i < 2 * N0) {
            int j = i - N0;
            int r = j / DINX, k = j % DINX;
            d_Wt0b[k * 3200 + r] = W0b[j];
        } else if (i < 2 * N0 + N1) {
            int j = i - 2 * N0;
            int r = j / K1, k = j % K1;
            d_Wt1f[(size_t)k * 3200 + r] = W1f[j];
        } else {
            int j = i - 2 * N0 - N1;
            int r = j / K1, k = j % K1;
            d_Wt1b[(size_t)k * 3200 + r] = W1b[j];
        }
    }
}

// ---------------- xg precompute: xg[dir][t][r][b] = bias[r] + sum_k Wt[k][r] * src[t][k][b] ----------------
template <int KK, int SSTR, int LAYER>
__global__ void k_xg(const float* __restrict__ bF, const float* __restrict__ bB)
{
    extern __shared__ float sx[];   // KK * 32 floats
    const int t = blockIdx.x;
    const int dir = blockIdx.y;
    const float* Wt   = (LAYER == 0) ? (dir ? d_Wt0b : d_Wt0f) : (dir ? d_Wt1b : d_Wt1f);
    const float* bias = dir ? bB : bF;
    const float* src  = (LAYER == 0) ? d_xT : d_h0T;
    const float* s0 = src + (size_t)t * SSTR * BB;

    for (int i = threadIdx.x; i < KK * BB / 4; i += blockDim.x)
        ((float4*)sx)[i] = ((const float4*)s0)[i];
    __syncthreads();

    float* out = d_xg + (size_t)(dir * TT + t) * 3200 * BB;
    for (int r = threadIdx.x; r < 3200; r += blockDim.x) {
        float acc[32];
        #pragma unroll
        for (int j = 0; j < 32; j++) acc[j] = 0.f;
        const float* wp = Wt + r;
        for (int k = 0; k < KK; k++) {
            float w = wp[(size_t)k * 3200];
            const float4* xv = (const float4*)(sx + k * 32);
            #pragma unroll
            for (int j = 0; j < 8; j++) {
                float4 v = xv[j];
                acc[4 * j + 0] = fmaf(w, v.x, acc[4 * j + 0]);
                acc[4 * j + 1] = fmaf(w, v.y, acc[4 * j + 1]);
                acc[4 * j + 2] = fmaf(w, v.z, acc[4 * j + 2]);
                acc[4 * j + 3] = fmaf(w, v.w, acc[4 * j + 3]);
            }
        }
        float bv = bias[r];
        float4* op = (float4*)(out + (size_t)r * BB);
        #pragma unroll
        for (int j = 0; j < 8; j++) {
            float4 v4;
            v4.x = acc[4 * j + 0] + bv;
            v4.y = acc[4 * j + 1] + bv;
            v4.z = acc[4 * j + 2] + bv;
            v4.w = acc[4 * j + 3] + bv;
            op[j] = v4;
        }
    }
}

// ---------------- hierarchical grid-wide barrier ----------------
__device__ __forceinline__ void gsync(unsigned& mygen)
{
    __syncthreads();
    if (threadIdx.x == 0) {
        __threadfence();
        int grp = blockIdx.x & 7;
        unsigned sz = (grp < 4) ? 19u : 18u;   // 148 = 4*19 + 4*18
        unsigned v = atomicAdd(&g_cnt[grp], 1u);
        if (v == sz - 1u) {
            g_cnt[grp] = 0u;
            __threadfence();
            unsigned m = atomicAdd(&g_master, 1u);
            if (m == 7u) {
                g_master = 0u;
                __threadfence();
                g_gen = mygen + 1u;
            }
        }
        while (g_gen == mygen) { }
        __threadfence();
    }
    __syncthreads();
    mygen++;
}

// ---------------- persistent bidirectional LSTM layer ----------------
// 148 blocks x 11 warps = 1628 warps; warp gw -> (dir = gw/800, unit u = gw%800), lane = batch.
// Per step: stage h_prev[dir] in smem, recurrent K=800 dot products; c stays in registers.
template <int LAYER>
__global__ void __launch_bounds__(NTHR, 1) k_layer(const float* __restrict__ WhhF,
                                                   const float* __restrict__ WhhB)
{
    extern __shared__ float sIn[];   // 2 segments of 800*32 floats
    const int warp = threadIdx.x >> 5;
    const int lane = threadIdx.x & 31;
    const int gw = blockIdx.x * NW + warp;
    const bool active = (gw < K1);
    const int dir = active ? (gw / HH) : 0;
    const int u   = active ? (gw % HH) : 0;

    float* hbuf = (LAYER == 0) ? d_h0T : d_h1T;
    const float* Whh = dir ? WhhB : WhhF;
    const float* w0 = Whh + (size_t)u * HH;
    const float* w1 = Whh + (size_t)(u + HH) * HH;
    const float* w2 = Whh + (size_t)(u + 2 * HH) * HH;
    const float* w3 = Whh + (size_t)(u + 3 * HH) * HH;

    const int r0 = blockIdx.x * NW;
    const int r1 = min(r0 + NW - 1, K1 - 1);
    const bool blkActive = (r0 < K1);
    const bool need0 = blkActive && (r0 < HH);
    const bool need1 = blkActive && (r1 >= HH);

    unsigned mygen = g_gen;
    float c = 0.f;

    for (int s = 0; s < TT; s++) {
        const int t = dir ? (TT - 1 - s) : s;
        if (s > 0) {
            gsync(mygen);
            const int tp0 = s - 1;
            const int tp1 = TT - s;
            const float4* src0 = (const float4*)(hbuf + (size_t)tp0 * (K1 * BB));
            const float4* src1 = (const float4*)(hbuf + (size_t)tp1 * (K1 * BB) + HH * BB);
            float4* dst0 = (float4*)(sIn);
            float4* dst1 = (float4*)(sIn + HH * BB);
            if (need0)
                for (int i = threadIdx.x; i < HH * BB / 4; i += NTHR) dst0[i] = src0[i];
            if (need1)
                for (int i = threadIdx.x; i < HH * BB / 4; i += NTHR) dst1[i] = src1[i];
            __syncthreads();
        }

        if (active) {
            const float* xg = d_xg + (size_t)(dir * TT + t) * 3200 * BB;
            float a0 = xg[(size_t)(u         ) * BB + lane];
            float a1 = xg[(size_t)(u +     HH) * BB + lane];
            float a2 = xg[(size_t)(u + 2 * HH) * BB + lane];
            float a3 = xg[(size_t)(u + 3 * HH) * BB + lane];

            if (s > 0) {
                const float* seg = sIn + dir * (HH * BB);
                #pragma unroll 2
                for (int k = 0; k < HH; k += 4) {
                    float4 W0 = *(const float4*)(w0 + k);
                    float4 W1 = *(const float4*)(w1 + k);
                    float4 W2 = *(const float4*)(w2 + k);
                    float4 W3 = *(const float4*)(w3 + k);
                    float v0 = seg[(k + 0) * BB + lane];
                    float v1 = seg[(k + 1) * BB + lane];
                    float v2 = seg[(k + 2) * BB + lane];
                    float v3 = seg[(k + 3) * BB + lane];
                    a0 = fmaf(W0.x, v0, a0); a0 = fmaf(W0.y, v1, a0); a0 = fmaf(W0.z, v2, a0); a0 = fmaf(W0.w, v3, a0);
                    a1 = fmaf(W1.x, v0, a1); a1 = fmaf(W1.y, v1, a1); a1 = fmaf(W1.z, v2, a1); a1 = fmaf(W1.w, v3, a1);
                    a2 = fmaf(W2.x, v0, a2); a2 = fmaf(W2.y, v1, a2); a2 = fmaf(W2.z, v2, a2); a2 = fmaf(W2.w, v3, a2);
                    a3 = fmaf(W3.x, v0, a3); a3 = fmaf(W3.y, v1, a3); a3 = fmaf(W3.z, v2, a3); a3 = fmaf(W3.w, v3, a3);
                }
            }

            float ig = 1.f / (1.f + expf(-a0));
            float fg = 1.f / (1.f + expf(-a1));
            float gg = tanhf(a2);
            float og = 1.f / (1.f + expf(-a3));
            c = (s == 0) ? (ig * gg) : (fg * c + ig * gg);
            float h = og * tanhf(c);

            hbuf[(size_t)t * (K1 * BB) + (size_t)(dir * HH + u) * BB + lane] = h;
        }
    }
}

// ---------------- fc + softmax + dihedral ----------------
#define RNN_OUT 1653
#define AA 60
__global__ void k_fc(const float* __restrict__ fcW, const float* __restrict__ fcb,
                     const float* __restrict__ alphabet)
{
    const int t = blockIdx.x;
    __shared__ float sbuf[256 * BB];
    __shared__ float slog[AA * 33];
    const int tid  = threadIdx.x;
    const int warp = tid >> 5;
    const int lane = tid & 31;

    float acc[8];
    #pragma unroll
    for (int j = 0; j < 8; j++) {
        int a = warp * 8 + j;
        acc[j] = (a < AA) ? fcb[a] : 0.f;
    }

    for (int chunk = 0; chunk < RNN_OUT; chunk += 256) {
        int nk = min(256, RNN_OUT - chunk);
        for (int i = tid; i < nk * BB; i += blockDim.x) {
            int r = chunk + (i >> 5);
            int b = i & 31;
            float v = (r < K1)
                ? d_h1T[(size_t)t * K1 * BB + (size_t)r * BB + b]
                : d_xT[(size_t)t * 64 * BB + (size_t)(r - K1) * BB + b];
            sbuf[i] = v;
        }
        __syncthreads();
        #pragma unroll
        for (int j = 0; j < 8; j++) {
            int a = warp * 8 + j;
            if (a < AA) {
                const float* wr = fcW + (size_t)a * RNN_OUT + chunk;
                float aj = acc[j];
                for (int k = 0; k < nk; k++)
                    aj = fmaf(__ldg(wr + k), sbuf[k * BB + lane], aj);
                acc[j] = aj;
            }
        }
        __syncthreads();
    }

    #pragma unroll
    for (int j = 0; j < 8; j++) {
        int a = warp * 8 + j;
        if (a < AA) slog[a * 33 + lane] = acc[j];
    }
    __syncthreads();

    if (tid < BB) {
        int b = tid;
        float mx = -1e30f;
        for (int a = 0; a < AA; a++) mx = fmaxf(mx, slog[a * 33 + b]);
        float sum = 0.f;
        for (int a = 0; a < AA; a++) {
            float e = expf(slog[a * 33 + b] - mx);
            slog[a * 33 + b] = e;
            sum += e;
        }
        float inv = 1.f / sum;
        float ss0 = 0, ss1 = 0, ss2 = 0, cc0 = 0, cc1 = 0, cc2 = 0;
        for (int a = 0; a < AA; a++) {
            float p = slog[a * 33 + b] * inv;
            float l0 = alphabet[a * 3 + 0], l1 = alphabet[a * 3 + 1], l2 = alphabet[a * 3 + 2];
            ss0 = fmaf(p, sinf(l0), ss0); cc0 = fmaf(p, cosf(l0), cc0);
            ss1 = fmaf(p, sinf(l1), ss1); cc1 = fmaf(p, cosf(l1), cc1);
            ss2 = fmaf(p, sinf(l2), ss2); cc2 = fmaf(p, cosf(l2), cc2);
        }
        d_dih[(t * BB + b) * 3 + 0] = atan2f(ss0, cc0);
        d_dih[(t * BB + b) * 3 + 1] = atan2f(ss1, cc1);
        d_dih[(t * BB + b) * 3 + 2] = atan2f(ss2, cc2);
    }
}

// ---------------- NeRF chain (sequential, one thread per batch) ----------------
struct V3 { float x, y, z; };
__device__ __forceinline__ V3 v3sub(V3 a, V3 b) { return {a.x - b.x, a.y - b.y, a.z - b.z}; }
__device__ __forceinline__ V3 v3cross(V3 a, V3 b) {
    return {a.y * b.z - a.z * b.y, a.z * b.x - a.x * b.z, a.x * b.y - a.y * b.x};
}
__device__ __forceinline__ V3 v3norm(V3 a) {
    float inv = 1.f / sqrtf(a.x * a.x + a.y * a.y + a.z * a.z + 1e-12f);
    return {a.x * inv, a.y * inv, a.z * inv};
}

__global__ void k_nerf(float* __restrict__ out)
{
    int b = threadIdx.x;
    if (b >= BB) return;

    V3 A  = {-0.70710678118654752f, 1.22474487139158905f, 0.f};
    V3 Bv = {-1.41421356237309505f, 0.f, 0.f};
    V3 C  = {0.f, 0.f, 0.f};

    const float bl[3] = {145.801f, 152.326f, 132.868f};
    const float ba[3] = {2.124f, 1.941f, 2.028f};
    float rct[3], rst[3];
    #pragma unroll
    for (int j = 0; j < 3; j++) {
        float th = 3.14159265358979323846f - ba[j];
        rct[j] = bl[j] * cosf(th);
        rst[j] = bl[j] * sinf(th);
    }

    for (int t = 0; t < TT; t++) {
        #pragma unroll
        for (int j = 0; j < 3; j++) {
            float phi = d_dih[(t * BB + b) * 3 + j];
            V3 p = {rct[j], cosf(phi) * rst[j], sinf(phi) * rst[j]};
            V3 bc = v3norm(v3sub(C, Bv));
            V3 n  = v3norm(v3cross(v3sub(Bv, A), bc));
            V3 nxbc = v3cross(n, bc);
            V3 coord = {
                C.x + p.x * bc.x + p.y * nxbc.x + p.z * n.x,
                C.y + p.x * bc.y + p.y * nxbc.y + p.z * n.y,
                C.z + p.x * bc.z + p.y * nxbc.z + p.z * n.z
            };
            size_t o = ((size_t)(3 * t + j) * BB + b) * 3;
            out[o + 0] = coord.x;
            out[o + 1] = coord.y;
            out[o + 2] = coord.z;
            A = Bv; Bv = C; C = coord;
        }
    }
}

// ---------------- launch ----------------
extern "C" void kernel_launch(void* const* d_in, const int* in_sizes, int n_in,
                              void* d_out, int out_size)
{
    int base = 2;
    if (base < n_in && in_sizes[base] == 1) base = 3;

    const int*   primary = (const int*)  d_in[0];
    const float* evo     = (const float*)d_in[1];
    const float* emb     = (const float*)d_in[base + 0];
    const float* Wih0f   = (const float*)d_in[base + 1];
    const float* Whh0f   = (const float*)d_in[base + 2];
    const float* b0f     = (const float*)d_in[base + 3];
    const float* Wih0b   = (const float*)d_in[base + 4];
    const float* Whh0b   = (const float*)d_in[base + 5];
    const float* b0b     = (const float*)d_in[base + 6];
    const float* Wih1f   = (const float*)d_in[base + 7];
    const float* Whh1f   = (const float*)d_in[base + 8];
    const float* b1f     = (const float*)d_in[base + 9];
    const float* Wih1b   = (const float*)d_in[base + 10];
    const float* Whh1b   = (const float*)d_in[base + 11];
    const float* b1b     = (const float*)d_in[base + 12];
    const float* fcW     = (const float*)d_in[base + 13];
    const float* fcb     = (const float*)d_in[base + 14];
    const float* alphabet= (const float*)d_in[base + 15];

    const int SMEM_SEG = 2 * HH * BB * sizeof(float);      // 204800
    const int SMEM_XG1 = K1 * BB * sizeof(float);          // 204800
    cudaFuncSetAttribute(k_layer<0>, cudaFuncAttributeMaxDynamicSharedMemorySize, SMEM_SEG);
    cudaFuncSetAttribute(k_layer<1>, cudaFuncAttributeMaxDynamicSharedMemorySize, SMEM_SEG);
    cudaFuncSetAttribute((const void*)k_xg<K1, K1, 1>, cudaFuncAttributeMaxDynamicSharedMemorySize, SMEM_XG1);

    k_prep<<<(TT * 64 * BB + 255) / 256, 256>>>(primary, evo, emb);
    k_trans<<<512, 256>>>(Wih0f, Wih0b, Wih1f, Wih1b);

    dim3 gxg(TT, 2, 1);
    k_xg<DINX, 64, 0><<<gxg, 256, DINX * BB * sizeof(float)>>>(b0f, b0b);
    k_layer<0><<<GRID, NTHR, SMEM_SEG>>>(Whh0f, Whh0b);
    k_xg<K1, K1, 1><<<gxg, 256, SMEM_XG1>>>(b1f, b1b);
    k_layer<1><<<GRID, NTHR, SMEM_SEG>>>(Whh1f, Whh1b);

    k_fc<<<TT, 256>>>(fcW, fcb, alphabet);
    k_nerf<<<1, 32>>>((float*)d_out);
}

// round 3
// speedup vs baseline: 1.4659x; 1.4659x over previous
#include <cuda_runtime.h>
#include <math.h>
#include <stdint.h>

#define TT 700
#define BB 32
#define HH 800
#define K1 1600
#define DINX 53
#define GRID 148
#define NW 11
#define NTHR (NW * 32)

// ---------------- scratch (static device globals; no allocation) ----------------
__device__ float d_xT [TT * 64 * BB];         // [t][k(64 padded)][b]
__device__ float d_h0T[TT * K1 * BB];         // [t][row 0..1599][b]  f=[0,800) b=[800,1600)
__device__ float d_h1T[TT * K1 * BB];
__device__ float d_xg [2 * TT * 3200 * BB];   // [dir][t][gate-row 0..3199][b]  (bias folded)
__device__ float d_Wt0f[DINX * 3200];         // transposed Wih0: [k][row]
__device__ float d_Wt0b[DINX * 3200];
__device__ float d_Wt1f[K1 * 3200];
__device__ float d_Wt1b[K1 * 3200];
__device__ float d_dih[TT * BB * 3];

// global barrier state (zero-initialized)
__device__ unsigned g_cnt[8];
__device__ unsigned g_master;
__device__ volatile unsigned g_gen;

// ---------------- small PTX helpers ----------------
__device__ __forceinline__ uint32_t smem_u32(const void* p) {
    uint32_t a;
    asm("{ .reg .u64 t; cvta.to.shared.u64 t, %1; cvt.u32.u64 %0, t; }" : "=r"(a) : "l"(p));
    return a;
}
__device__ __forceinline__ void mbar_init(uint32_t mbar, uint32_t count) {
    asm volatile("mbarrier.init.shared.b64 [%0], %1;" :: "r"(mbar), "r"(count) : "memory");
}
__device__ __forceinline__ void mbar_expect_tx(uint32_t mbar, uint32_t bytes) {
    asm volatile("mbarrier.arrive.expect_tx.shared.b64 _, [%0], %1;" :: "r"(mbar), "r"(bytes) : "memory");
}
__device__ __forceinline__ void bulk_g2s(uint32_t dst, const void* src, uint32_t bytes, uint32_t mbar) {
    asm volatile("cp.async.bulk.shared::cluster.global.mbarrier::complete_tx::bytes [%0], [%1], %2, [%3];"
                 :: "r"(dst), "l"(src), "r"(bytes), "r"(mbar) : "memory");
}
__device__ __forceinline__ void mbar_wait(uint32_t mbar, uint32_t phase) {
    asm volatile(
        "{\n\t.reg .pred P1;\n\t"
        "W%=:\n\t"
        "mbarrier.try_wait.parity.acquire.cta.shared::cta.b64 P1, [%0], %1, 0x989680;\n\t"
        "@P1 bra D%=;\n\t"
        "bra W%=;\n\t"
        "D%=:\n\t}"
        :: "r"(mbar), "r"(phase) : "memory");
}

// ---------------- prep: x = concat(emb[primary], evolutionary), transposed ----------------
__global__ void k_prep(const int* __restrict__ primary,
                       const float* __restrict__ evo,
                       const float* __restrict__ emb)
{
    int idx = blockIdx.x * blockDim.x + threadIdx.x;
    if (idx >= TT * 64 * BB) return;
    int b = idx & 31;
    int k = (idx >> 5) & 63;
    int t = idx >> 11;
    float v = 0.f;
    if (k < 32) {
        int aa = primary[t * BB + b];
        v = emb[aa * 32 + k];
    } else if (k < DINX) {
        v = evo[(t * BB + b) * 21 + (k - 32)];
    }
    d_xT[idx] = v;
}

// ---------------- transpose input weights into [k][row] ----------------
__global__ void k_trans(const float* __restrict__ W0f, const float* __restrict__ W0b,
                        const float* __restrict__ W1f, const float* __restrict__ W1b)
{
    const int N0 = 3200 * DINX;
    const int N1 = 3200 * K1;
    const int NT = 2 * N0 + 2 * N1;
    for (int i = blockIdx.x * blockDim.x + threadIdx.x; i < NT; i += gridDim.x * blockDim.x) {
        if (i < N0) {
            int r = i / DINX, k = i % DINX;
            d_Wt0f[k * 3200 + r] = W0f[i];
        } else if (i < 2 * N0) {
            int j = i - N0;
            int r = j / DINX, k = j % DINX;
            d_Wt0b[k * 3200 + r] = W0b[j];
        } else if (i < 2 * N0 + N1) {
            int j = i - 2 * N0;
            int r = j / K1, k = j % K1;
            d_Wt1f[(size_t)k * 3200 + r] = W1f[j];
        } else {
            int j = i - 2 * N0 - N1;
            int r = j / K1, k = j % K1;
            d_Wt1b[(size_t)k * 3200 + r] = W1b[j];
        }
    }
}

// ---------------- xg precompute: xg[dir][t][r][b] = bias[r] + sum_k Wt[k][r] * src[t][k][b] ----------------
template <int KK, int SSTR, int LAYER>
__global__ void k_xg(const float* __restrict__ bF, const float* __restrict__ bB)
{
    extern __shared__ float sx[];   // KK * 32 floats
    const int t = blockIdx.x;
    const int dir = blockIdx.y;
    const float* Wt   = (LAYER == 0) ? (dir ? d_Wt0b : d_Wt0f) : (dir ? d_Wt1b : d_Wt1f);
    const float* bias = dir ? bB : bF;
    const float* src  = (LAYER == 0) ? d_xT : d_h0T;
    const float* s0 = src + (size_t)t * SSTR * BB;

    for (int i = threadIdx.x; i < KK * BB / 4; i += blockDim.x)
        ((float4*)sx)[i] = ((const float4*)s0)[i];
    __syncthreads();

    float* out = d_xg + (size_t)(dir * TT + t) * 3200 * BB;
    for (int r = threadIdx.x; r < 3200; r += blockDim.x) {
        float acc[32];
        #pragma unroll
        for (int j = 0; j < 32; j++) acc[j] = 0.f;
        const float* wp = Wt + r;
        for (int k = 0; k < KK; k++) {
            float w = wp[(size_t)k * 3200];
            const float4* xv = (const float4*)(sx + k * 32);
            #pragma unroll
            for (int j = 0; j < 8; j++) {
                float4 v = xv[j];
                acc[4 * j + 0] = fmaf(w, v.x, acc[4 * j + 0]);
                acc[4 * j + 1] = fmaf(w, v.y, acc[4 * j + 1]);
                acc[4 * j + 2] = fmaf(w, v.z, acc[4 * j + 2]);
                acc[4 * j + 3] = fmaf(w, v.w, acc[4 * j + 3]);
            }
        }
        float bv = bias[r];
        float4* op = (float4*)(out + (size_t)r * BB);
        #pragma unroll
        for (int j = 0; j < 8; j++) {
            float4 v4;
            v4.x = acc[4 * j + 0] + bv;
            v4.y = acc[4 * j + 1] + bv;
            v4.z = acc[4 * j + 2] + bv;
            v4.w = acc[4 * j + 3] + bv;
            op[j] = v4;
        }
    }
}

// ---------------- hierarchical grid-wide barrier ----------------
__device__ __forceinline__ void gsync(unsigned& mygen)
{
    __syncthreads();
    if (threadIdx.x == 0) {
        __threadfence();
        int grp = blockIdx.x & 7;
        unsigned sz = (grp < 4) ? 19u : 18u;   // 148 = 4*19 + 4*18
        unsigned v = atomicAdd(&g_cnt[grp], 1u);
        if (v == sz - 1u) {
            g_cnt[grp] = 0u;
            __threadfence();
            unsigned m = atomicAdd(&g_master, 1u);
            if (m == 7u) {
                g_master = 0u;
                __threadfence();
                g_gen = mygen + 1u;
            }
        }
        while (g_gen == mygen) { }
        __threadfence();
    }
    __syncthreads();
    mygen++;
}

// ---------------- persistent bidirectional LSTM layer ----------------
// 148 blocks; dir = bid&1 (74 blocks per direction), unit u = (bid>>1)*11 + warp.
// h_prev staged per step via ONE cp.async.bulk (100KB) into smem; weights stay
// L1-resident (no big LDG staging, ~125KB L1D left); cell state c in registers.
template <int LAYER>
__global__ void __launch_bounds__(NTHR, 1) k_layer(const float* __restrict__ WhhF,
                                                   const float* __restrict__ WhhB)
{
    extern __shared__ float sH[];   // HH*BB floats + mbarrier at offset HH*BB
    const int warp = threadIdx.x >> 5;
    const int lane = threadIdx.x & 31;
    const int dir  = blockIdx.x & 1;
    const int u    = (blockIdx.x >> 1) * NW + warp;   // 0..813
    const bool active = (u < HH);

    float* hbuf = (LAYER == 0) ? d_h0T : d_h1T;
    const float* Whh = dir ? WhhB : WhhF;
    const int uu = active ? u : 0;
    const float* w0 = Whh + (size_t)uu * HH;
    const float* w1 = Whh + (size_t)(uu + HH) * HH;
    const float* w2 = Whh + (size_t)(uu + 2 * HH) * HH;
    const float* w3 = Whh + (size_t)(uu + 3 * HH) * HH;

    uint32_t sbase = smem_u32(sH);
    uint32_t mbar = sbase + HH * BB * 4;
    if (threadIdx.x == 0) mbar_init(mbar, 1);
    __syncthreads();

    unsigned mygen = g_gen;
    uint32_t phase = 0;
    float c = 0.f;

    for (int s = 0; s < TT; s++) {
        const int t = dir ? (TT - 1 - s) : s;
        if (s > 0) {
            gsync(mygen);
            const int tp = dir ? (t + 1) : (t - 1);
            const float* src = hbuf + (size_t)tp * (K1 * BB) + (size_t)dir * HH * BB;
            if (threadIdx.x == 0) {
                mbar_expect_tx(mbar, HH * BB * 4);
                bulk_g2s(sbase, src, HH * BB * 4, mbar);
            }
            mbar_wait(mbar, phase);
            phase ^= 1;
        }

        if (active) {
            // hoist xg loads (DRAM) so they land while the dot product runs
            const float* xg = d_xg + (size_t)(dir * TT + t) * 3200 * BB;
            float x0 = __ldg(xg + (size_t)(uu         ) * BB + lane);
            float x1 = __ldg(xg + (size_t)(uu +     HH) * BB + lane);
            float x2 = __ldg(xg + (size_t)(uu + 2 * HH) * BB + lane);
            float x3 = __ldg(xg + (size_t)(uu + 3 * HH) * BB + lane);

            float d0 = 0.f, d1 = 0.f, d2 = 0.f, d3 = 0.f;
            if (s > 0) {
                #pragma unroll 2
                for (int k = 0; k < HH; k += 4) {
                    float4 W0 = *(const float4*)(w0 + k);
                    float4 W1 = *(const float4*)(w1 + k);
                    float4 W2 = *(const float4*)(w2 + k);
                    float4 W3 = *(const float4*)(w3 + k);
                    float v0 = sH[(k + 0) * BB + lane];
                    float v1 = sH[(k + 1) * BB + lane];
                    float v2 = sH[(k + 2) * BB + lane];
                    float v3 = sH[(k + 3) * BB + lane];
                    d0 = fmaf(W0.x, v0, d0); d0 = fmaf(W0.y, v1, d0); d0 = fmaf(W0.z, v2, d0); d0 = fmaf(W0.w, v3, d0);
                    d1 = fmaf(W1.x, v0, d1); d1 = fmaf(W1.y, v1, d1); d1 = fmaf(W1.z, v2, d1); d1 = fmaf(W1.w, v3, d1);
                    d2 = fmaf(W2.x, v0, d2); d2 = fmaf(W2.y, v1, d2); d2 = fmaf(W2.z, v2, d2); d2 = fmaf(W2.w, v3, d2);
                    d3 = fmaf(W3.x, v0, d3); d3 = fmaf(W3.y, v1, d3); d3 = fmaf(W3.z, v2, d3); d3 = fmaf(W3.w, v3, d3);
                }
            }
            float a0 = x0 + d0;
            float a1 = x1 + d1;
            float a2 = x2 + d2;
            float a3 = x3 + d3;

            float ig = 1.f / (1.f + expf(-a0));
            float fg = 1.f / (1.f + expf(-a1));
            float gg = tanhf(a2);
            float og = 1.f / (1.f + expf(-a3));
            c = (s == 0) ? (ig * gg) : (fg * c + ig * gg);
            float h = og * tanhf(c);

            hbuf[(size_t)t * (K1 * BB) + (size_t)(dir * HH + uu) * BB + lane] = h;
        }
    }
}

// ---------------- fc + softmax + dihedral ----------------
#define RNN_OUT 1653
#define AA 60
__global__ void k_fc(const float* __restrict__ fcW, const float* __restrict__ fcb,
                     const float* __restrict__ alphabet)
{
    const int t = blockIdx.x;
    __shared__ float sbuf[256 * BB];
    __shared__ float slog[AA * 33];
    const int tid  = threadIdx.x;
    const int warp = tid >> 5;
    const int lane = tid & 31;

    float acc[8];
    #pragma unroll
    for (int j = 0; j < 8; j++) {
        int a = warp * 8 + j;
        acc[j] = (a < AA) ? fcb[a] : 0.f;
    }

    for (int chunk = 0; chunk < RNN_OUT; chunk += 256) {
        int nk = min(256, RNN_OUT - chunk);
        for (int i = tid; i < nk * BB; i += blockDim.x) {
            int r = chunk + (i >> 5);
            int b = i & 31;
            float v = (r < K1)
                ? d_h1T[(size_t)t * K1 * BB + (size_t)r * BB + b]
                : d_xT[(size_t)t * 64 * BB + (size_t)(r - K1) * BB + b];
            sbuf[i] = v;
        }
        __syncthreads();
        #pragma unroll
        for (int j = 0; j < 8; j++) {
            int a = warp * 8 + j;
            if (a < AA) {
                const float* wr = fcW + (size_t)a * RNN_OUT + chunk;
                float aj = acc[j];
                for (int k = 0; k < nk; k++)
                    aj = fmaf(__ldg(wr + k), sbuf[k * BB + lane], aj);
                acc[j] = aj;
            }
        }
        __syncthreads();
    }

    #pragma unroll
    for (int j = 0; j < 8; j++) {
        int a = warp * 8 + j;
        if (a < AA) slog[a * 33 + lane] = acc[j];
    }
    __syncthreads();

    if (tid < BB) {
        int b = tid;
        float mx = -1e30f;
        for (int a = 0; a < AA; a++) mx = fmaxf(mx, slog[a * 33 + b]);
        float sum = 0.f;
        for (int a = 0; a < AA; a++) {
            float e = expf(slog[a * 33 + b] - mx);
            slog[a * 33 + b] = e;
            sum += e;
        }
        float inv = 1.f / sum;
        float ss0 = 0, ss1 = 0, ss2 = 0, cc0 = 0, cc1 = 0, cc2 = 0;
        for (int a = 0; a < AA; a++) {
            float p = slog[a * 33 + b] * inv;
            float l0 = alphabet[a * 3 + 0], l1 = alphabet[a * 3 + 1], l2 = alphabet[a * 3 + 2];
            ss0 = fmaf(p, sinf(l0), ss0); cc0 = fmaf(p, cosf(l0), cc0);
            ss1 = fmaf(p, sinf(l1), ss1); cc1 = fmaf(p, cosf(l1), cc1);
            ss2 = fmaf(p, sinf(l2), ss2); cc2 = fmaf(p, cosf(l2), cc2);
        }
        d_dih[(t * BB + b) * 3 + 0] = atan2f(ss0, cc0);
        d_dih[(t * BB + b) * 3 + 1] = atan2f(ss1, cc1);
        d_dih[(t * BB + b) * 3 + 2] = atan2f(ss2, cc2);
    }
}

// ---------------- NeRF chain (sequential, one thread per batch) ----------------
struct V3 { float x, y, z; };
__device__ __forceinline__ V3 v3sub(V3 a, V3 b) { return {a.x - b.x, a.y - b.y, a.z - b.z}; }
__device__ __forceinline__ V3 v3cross(V3 a, V3 b) {
    return {a.y * b.z - a.z * b.y, a.z * b.x - a.x * b.z, a.x * b.y - a.y * b.x};
}
__device__ __forceinline__ V3 v3norm(V3 a) {
    float inv = 1.f / sqrtf(a.x * a.x + a.y * a.y + a.z * a.z + 1e-12f);
    return {a.x * inv, a.y * inv, a.z * inv};
}

__global__ void k_nerf(float* __restrict__ out)
{
    int b = threadIdx.x;
    if (b >= BB) return;

    V3 A  = {-0.70710678118654752f, 1.22474487139158905f, 0.f};
    V3 Bv = {-1.41421356237309505f, 0.f, 0.f};
    V3 C  = {0.f, 0.f, 0.f};

    const float bl[3] = {145.801f, 152.326f, 132.868f};
    const float ba[3] = {2.124f, 1.941f, 2.028f};
    float rct[3], rst[3];
    #pragma unroll
    for (int j = 0; j < 3; j++) {
        float th = 3.14159265358979323846f - ba[j];
        rct[j] = bl[j] * cosf(th);
        rst[j] = bl[j] * sinf(th);
    }

    for (int t = 0; t < TT; t++) {
        #pragma unroll
        for (int j = 0; j < 3; j++) {
            float phi = d_dih[(t * BB + b) * 3 + j];
            V3 p = {rct[j], cosf(phi) * rst[j], sinf(phi) * rst[j]};
            V3 bc = v3norm(v3sub(C, Bv));
            V3 n  = v3norm(v3cross(v3sub(Bv, A), bc));
            V3 nxbc = v3cross(n, bc);
            V3 coord = {
                C.x + p.x * bc.x + p.y * nxbc.x + p.z * n.x,
                C.y + p.x * bc.y + p.y * nxbc.y + p.z * n.y,
                C.z + p.x * bc.z + p.y * nxbc.z + p.z * n.z
            };
            size_t o = ((size_t)(3 * t + j) * BB + b) * 3;
            out[o + 0] = coord.x;
            out[o + 1] = coord.y;
            out[o + 2] = coord.z;
            A = Bv; Bv = C; C = coord;
        }
    }
}

// ---------------- launch ----------------
extern "C" void kernel_launch(void* const* d_in, const int* in_sizes, int n_in,
                              void* d_out, int out_size)
{
    int base = 2;
    if (base < n_in && in_sizes[base] == 1) base = 3;

    const int*   primary = (const int*)  d_in[0];
    const float* evo     = (const float*)d_in[1];
    const float* emb     = (const float*)d_in[base + 0];
    const float* Wih0f   = (const float*)d_in[base + 1];
    const float* Whh0f   = (const float*)d_in[base + 2];
    const float* b0f     = (const float*)d_in[base + 3];
    const float* Wih0b   = (const float*)d_in[base + 4];
    const float* Whh0b   = (const float*)d_in[base + 5];
    const float* b0b     = (const float*)d_in[base + 6];
    const float* Wih1f   = (const float*)d_in[base + 7];
    const float* Whh1f   = (const float*)d_in[base + 8];
    const float* b1f     = (const float*)d_in[base + 9];
    const float* Wih1b   = (const float*)d_in[base + 10];
    const float* Whh1b   = (const float*)d_in[base + 11];
    const float* b1b     = (const float*)d_in[base + 12];
    const float* fcW     = (const float*)d_in[base + 13];
    const float* fcb     = (const float*)d_in[base + 14];
    const float* alphabet= (const float*)d_in[base + 15];

    const int SMEM_SEG = HH * BB * sizeof(float) + 64;     // 102464 (h tile + mbarrier)
    const int SMEM_XG1 = K1 * BB * sizeof(float);          // 204800
    cudaFuncSetAttribute(k_layer<0>, cudaFuncAttributeMaxDynamicSharedMemorySize, SMEM_SEG);
    cudaFuncSetAttribute(k_layer<1>, cudaFuncAttributeMaxDynamicSharedMemorySize, SMEM_SEG);
    cudaFuncSetAttribute((const void*)k_xg<K1, K1, 1>, cudaFuncAttributeMaxDynamicSharedMemorySize, SMEM_XG1);

    k_prep<<<(TT * 64 * BB + 255) / 256, 256>>>(primary, evo, emb);
    k_trans<<<512, 256>>>(Wih0f, Wih0b, Wih1f, Wih1b);

    dim3 gxg(TT, 2, 1);
    k_xg<DINX, 64, 0><<<gxg, 256, DINX * BB * sizeof(float)>>>(b0f, b0b);
    k_layer<0><<<GRID, NTHR, SMEM_SEG>>>(Whh0f, Whh0b);
    k_xg<K1, K1, 1><<<gxg, 256, SMEM_XG1>>>(b1f, b1b);
    k_layer<1><<<GRID, NTHR, SMEM_SEG>>>(Whh1f, Whh1b);

    k_fc<<<TT, 256>>>(fcW, fcb, alphabet);
    k_nerf<<<1, 32>>>((float*)d_out);
}